// round 5
// baseline (speedup 1.0000x reference)
#include <cuda_runtime.h>
#include <mma.h>

using namespace nvcuda;

#define N_NODES 100000
#define N_EDGES 1600000
#define IN_DIM  128
#define HID_DIM 64
#define GB      782          // ceil(N_NODES/128) gemm tile blocks
#define CB      1024         // count blocks riding along with gemm1
#define SB      98           // scan blocks (ceil(N_NODES/1024)), < 148 SMs

// ------------------------- device scratch (no allocs allowed) ---------------
// d_cnt / d_flag start zeroed (BSS) and are re-zeroed at the end of every call
// by the final aggregation kernel, so every invocation sees identical state.
__device__ int   d_cnt [N_NODES];                       // edge count per dst
__device__ int   d_rs  [N_NODES];                       // CSR row starts
__device__ int   d_fill[N_NODES];                       // fill cursors
__device__ float d_dinv[N_NODES];                       // 1/sqrt(deg) (deg=cnt+1)
__device__ __align__(16) int2  d_ew[N_EDGES];           // {src, w=dinv_s*dinv_d}
__device__ __align__(16) float d_bufA[(size_t)N_NODES * HID_DIM]; // GEMM out
__device__ __align__(16) float d_bufB[(size_t)N_NODES * HID_DIM]; // activation
__device__ int   d_agg [SB];                            // scan block aggregates
__device__ int   d_flag[SB];                            // publish flags

// ------------------------- TF32 GEMM (+ optional fused degree count) --------
// Block tile 128x64. 8 warps, each owns 16 rows (4x m16n16k8 accum frags).
// Blocks [GB, GB+CB) instead perform the per-dst edge count (layer 1 only).
#define SA_LD 40
#define SO_LD 68
#define SW_ELE (32 * 64)
#define SMEM_FLOATS 8704

template <int K, bool A_IS_PARAM, bool COUNT>
__global__ __launch_bounds__(256) void k_gemm_tf32(const float* __restrict__ Aparam,
                                                   const float* __restrict__ W,
                                                   const int* __restrict__ dst) {
    __shared__ __align__(16) float smem[SMEM_FLOATS];
    if (COUNT && blockIdx.x >= GB) {                    // fused degree count
        int e0 = (blockIdx.x - GB) * 256 + threadIdx.x;
        for (int e = e0; e < N_EDGES; e += CB * 256)
            atomicAdd(&d_cnt[dst[e]], 1);
        return;
    }
    float* sW = smem;                                   // 32 x 64
    float* sA = smem + SW_ELE;                          // 128 x SA_LD
    const float* A = A_IS_PARAM ? Aparam : (const float*)d_bufB;

    int tid    = threadIdx.x;
    int warpId = tid >> 5;
    int r0     = blockIdx.x * 128;
    int wrow   = warpId * 16;

    wmma::fragment<wmma::matrix_a, 16, 16, 8, wmma::precision::tf32, wmma::row_major> fa;
    wmma::fragment<wmma::matrix_b, 16, 16, 8, wmma::precision::tf32, wmma::row_major> fb;
    wmma::fragment<wmma::accumulator, 16, 16, 8, float> fc[4];
#pragma unroll
    for (int n = 0; n < 4; ++n) wmma::fill_fragment(fc[n], 0.0f);

    for (int kc = 0; kc < K; kc += 32) {
#pragma unroll
        for (int u = 0; u < 2; ++u) {                   // W chunk: 32x64
            int idx = u * 256 + tid;
            float4 v = *(const float4*)&W[(size_t)kc * 64 + idx * 4];
            *(float4*)&sW[idx * 4] = v;
        }
#pragma unroll
        for (int u = 0; u < 4; ++u) {                   // A chunk: 128x32
            int idx = u * 256 + tid;
            int row = idx >> 3;
            int c4  = idx & 7;
            int r   = r0 + row;
            float4 v = make_float4(0.f, 0.f, 0.f, 0.f);
            if (r < N_NODES)
                v = *(const float4*)&A[(size_t)r * K + kc + c4 * 4];
            *(float4*)&sA[row * SA_LD + c4 * 4] = v;
        }
        __syncthreads();
#pragma unroll
        for (int kk = 0; kk < 32; kk += 8) {
            wmma::load_matrix_sync(fa, &sA[wrow * SA_LD + kk], SA_LD);
#pragma unroll
            for (int i = 0; i < fa.num_elements; ++i)
                fa.x[i] = wmma::__float_to_tf32(fa.x[i]);
#pragma unroll
            for (int n = 0; n < 4; ++n) {
                wmma::load_matrix_sync(fb, &sW[kk * 64 + n * 16], 64);
#pragma unroll
                for (int i = 0; i < fb.num_elements; ++i)
                    fb.x[i] = wmma::__float_to_tf32(fb.x[i]);
                wmma::mma_sync(fc[n], fa, fb, fc[n]);
            }
        }
        __syncthreads();
    }

    float* sOut = smem;                                 // 128 x SO_LD
#pragma unroll
    for (int n = 0; n < 4; ++n)
        wmma::store_matrix_sync(&sOut[wrow * SO_LD + n * 16], fc[n], SO_LD,
                                wmma::mem_row_major);
    __syncthreads();
#pragma unroll
    for (int u = 0; u < 8; ++u) {
        int idx = u * 256 + tid;
        int row = idx >> 4;
        int c4  = idx & 15;
        int r   = r0 + row;
        if (r < N_NODES) {
            float4 v = *(float4*)&sOut[row * SO_LD + c4 * 4];
            *(float4*)&d_bufA[(size_t)r * 64 + c4 * 4] = v;
        }
    }
}

// ------------------------- single-pass scan (row starts + dinv) -------------
// Each block scans 1024 counts; publishes aggregate, then sums ALL predecessor
// aggregates (lane-parallel; no serial chain). All SB blocks are resident.
__global__ __launch_bounds__(256) void k_scan() {
    __shared__ int sm[256];
    __shared__ int sBase;
    int tid = threadIdx.x, bid = blockIdx.x;
    int base = bid * 1024 + tid * 4;
    int c[4], v[4];
    int s = 0;
#pragma unroll
    for (int j = 0; j < 4; ++j) {
        int idx = base + j;
        c[j] = (idx < N_NODES) ? d_cnt[idx] : 0;
        v[j] = s; s += c[j];
    }
    sm[tid] = s;
    __syncthreads();
#pragma unroll
    for (int off = 1; off < 256; off <<= 1) {
        int t = (tid >= off) ? sm[tid - off] : 0;
        __syncthreads();
        sm[tid] += t;
        __syncthreads();
    }
    if (tid == 0) {                                     // publish aggregate
        d_agg[bid] = sm[255];
        __threadfence();
        *((volatile int*)&d_flag[bid]) = 1;
    }
    if (tid < 32) {                                     // lookback: sum preds
        int acc = 0;
        for (int i = tid; i < bid; i += 32) {
            while (*((volatile int*)&d_flag[i]) == 0) {}
            acc += *((volatile int*)&d_agg[i]);
        }
#pragma unroll
        for (int off = 16; off; off >>= 1)
            acc += __shfl_down_sync(0xffffffffu, acc, off);
        if (tid == 0) sBase = acc;
    }
    __syncthreads();
    int excl = (tid == 0) ? 0 : sm[tid - 1];
    int off0 = sBase + excl;
#pragma unroll
    for (int j = 0; j < 4; ++j) {
        int idx = base + j;
        if (idx < N_NODES) {
            int r = off0 + v[j];
            d_rs[idx]   = r;
            d_fill[idx] = r;
            d_dinv[idx] = rsqrtf((float)(c[j] + 1));    // +1: self-loop
        }
    }
}

// ------------------------- CSR fill with fused edge weights -----------------
__global__ void k_fill(const int* __restrict__ src,
                       const int* __restrict__ dst) {
    int e = blockIdx.x * blockDim.x + threadIdx.x;
    if (e < N_EDGES) {
        int d = dst[e];
        int s = src[e];
        int p = atomicAdd(&d_fill[d], 1);
        float w = d_dinv[s] * d_dinv[d];
        d_ew[p] = make_int2(s, __float_as_int(w));
    }
}

// ------------------------- pull aggregation (warp per node) -----------------
// out[i] = relu(sum_e w_e*g[src] + dinv_i^2*g[i] + b)
// FINAL: fuse 64->1 FC head; also restore d_cnt/d_flag to zero for next call.
template <bool FINAL>
__global__ __launch_bounds__(256) void k_aggr(const float* __restrict__ bias,
                                              const float* __restrict__ Wfc,
                                              const float* __restrict__ bfc,
                                              float* __restrict__ outp) {
    int gw = (blockIdx.x * blockDim.x + threadIdx.x) >> 5;
    if (gw >= N_NODES) return;
    int lane = threadIdx.x & 31;
    const float2* gp = (const float2*)d_bufA;           // lane owns dims 2l,2l+1

    int start = d_rs[gw];
    int cnt   = d_cnt[gw];
    float dv  = d_dinv[gw];
    float di2 = dv * dv;

    float2 g = gp[(size_t)gw * 32 + lane];
    float2 a0 = make_float2(di2 * g.x, di2 * g.y);      // self-loop term
    float2 a1 = make_float2(0.f, 0.f);
    float2 a2 = make_float2(0.f, 0.f);
    float2 a3 = make_float2(0.f, 0.f);

    int t = 0;
    for (; t + 4 <= cnt; t += 4) {
        int2 r0 = d_ew[start + t + 0];
        int2 r1 = d_ew[start + t + 1];
        int2 r2 = d_ew[start + t + 2];
        int2 r3 = d_ew[start + t + 3];
        float2 v0 = gp[(size_t)r0.x * 32 + lane];
        float2 v1 = gp[(size_t)r1.x * 32 + lane];
        float2 v2 = gp[(size_t)r2.x * 32 + lane];
        float2 v3 = gp[(size_t)r3.x * 32 + lane];
        float w0 = __int_as_float(r0.y), w1 = __int_as_float(r1.y);
        float w2 = __int_as_float(r2.y), w3 = __int_as_float(r3.y);
        a0.x = fmaf(w0, v0.x, a0.x); a0.y = fmaf(w0, v0.y, a0.y);
        a1.x = fmaf(w1, v1.x, a1.x); a1.y = fmaf(w1, v1.y, a1.y);
        a2.x = fmaf(w2, v2.x, a2.x); a2.y = fmaf(w2, v2.y, a2.y);
        a3.x = fmaf(w3, v3.x, a3.x); a3.y = fmaf(w3, v3.y, a3.y);
    }
    for (; t < cnt; ++t) {
        int2 r = d_ew[start + t];
        float2 v = gp[(size_t)r.x * 32 + lane];
        float w = __int_as_float(r.y);
        a0.x = fmaf(w, v.x, a0.x); a0.y = fmaf(w, v.y, a0.y);
    }

    float2 bb = ((const float2*)bias)[lane];
    float h0 = (a0.x + a1.x) + (a2.x + a3.x) + bb.x;
    float h1 = (a0.y + a1.y) + (a2.y + a3.y) + bb.y;
    h0 = fmaxf(h0, 0.f);
    h1 = fmaxf(h1, 0.f);

    if (!FINAL) {
        ((float2*)d_bufB)[(size_t)gw * 32 + lane] = make_float2(h0, h1);
    } else {
        float2 w = ((const float2*)Wfc)[lane];
        float p = h0 * w.x + h1 * w.y;
#pragma unroll
        for (int off = 16; off; off >>= 1)
            p += __shfl_down_sync(0xffffffffu, p, off);
        if (lane == 0) outp[gw] = p + bfc[0];
        // restore invariant state for the next invocation
        if (lane == 1) d_cnt[gw] = 0;
        if (lane == 2 && gw < SB) d_flag[gw] = 0;
    }
}

// ------------------------- launch ------------------------------------------
extern "C" void kernel_launch(void* const* d_in, const int* in_sizes, int n_in,
                              void* d_out, int out_size) {
    const float* x    = (const float*)d_in[0];
    const int*   ei   = (const int*)d_in[1];   // JAX x64 disabled: int32
    const float* W1   = (const float*)d_in[2];
    const float* b1   = (const float*)d_in[3];
    const float* W2   = (const float*)d_in[4];
    const float* b2   = (const float*)d_in[5];
    const float* Wfc  = (const float*)d_in[6];
    const float* bfc  = (const float*)d_in[7];
    float*       out  = (float*)d_out;

    const int* srcp = ei;              // edge_index[0]
    const int* dstp = ei + N_EDGES;    // edge_index[1]

    const int EB = (N_EDGES + 255) / 256;
    const int AB = (N_NODES * 32 + 255) / 256;   // warp per node

    // gemm1 fused with degree count (independent work shares one launch)
    k_gemm_tf32<IN_DIM, true, true ><<<GB + CB, 256>>>(x, W1, dstp);
    k_scan<<<SB, 256>>>();
    k_fill<<<EB, 256>>>(srcp, dstp);
    k_aggr<false><<<AB, 256>>>(b1, Wfc, bfc, out);
    // layer 2 + fused FC head (+ state restore)
    k_gemm_tf32<HID_DIM, false, false><<<GB, 256>>>(x /*unused*/, W2, nullptr);
    k_aggr<true ><<<AB, 256>>>(b2, Wfc, bfc, out);
}